// round 14
// baseline (speedup 1.0000x reference)
#include <cuda_runtime.h>
#include <cuda_fp16.h>

// ---------------- problem constants ----------------
#define MAXN 50000
#define MAXE 1600000
#define HID 128
#define HEADS 4
#define NGRAPH 64
#define SCAN_B 1024

// ---------------- scratch (static device memory; no allocations) ----------------
__device__ __align__(256) __half g_xlh[(size_t)MAXN * HID];  // fp16 xl table (gathered per edge)
__device__ __align__(256) float  g_xr [(size_t)MAXN * HID];  // fp32 xr table (read once per node)
__device__ __align__(256) float  g_h1[(size_t)MAXN * HID];
__device__ __align__(256) float  g_h2[(size_t)MAXN * HID];
__device__ __align__(256) int    g_src[MAXE + MAXN];
__device__ __align__(256) int    g_dst[MAXE + MAXN];
__device__ __align__(256) int    g_csr[MAXE + MAXN];
__device__ __align__(256) int    g_deg[MAXN];
__device__ __align__(256) int    g_rowstart[MAXN + 1];
__device__ __align__(256) int    g_cursor[MAXN];
__device__ __align__(256) int    g_batch[MAXN];
__device__ int   g_bsum[(MAXN + SCAN_B - 1) / SCAN_B];
__device__ int   g_total;
__device__ float g_pool[NGRAPH * HID];
__device__ float g_cnt[NGRAPH];
__device__ int   g_is64;

// ---------------- dtype detect ----------------
__global__ void detect_kernel(const unsigned* __restrict__ p)
{
    if (threadIdx.x == 0) {
        unsigned o = 0;
        for (int i = 0; i < 256; i++) o |= p[2 * i + 1];
        g_is64 = (o == 0) ? 1 : 0;
    }
}

__device__ __forceinline__ int load_idx(const void* p, int i, int is64, int N)
{
    long long v = is64 ? ((const long long*)p)[i] : (long long)((const int*)p)[i];
    int r = (int)v;
    return r < 0 ? 0 : (r >= N ? N - 1 : r);
}

__global__ void zero_deg(int N)
{
    int i = blockIdx.x * blockDim.x + threadIdx.x;
    if (i < N) g_deg[i] = 0;
}

__global__ void convert_kernel(const void* __restrict__ ei, const void* __restrict__ batch,
                               int E, int N)
{
    int is64 = g_is64;
    int ET = E + N;
    for (int i = blockIdx.x * blockDim.x + threadIdx.x; i < ET;
         i += gridDim.x * blockDim.x) {
        int s, d;
        if (i < E) {
            s = load_idx(ei, i, is64, N);
            d = load_idx(ei, E + i, is64, N);
        } else {
            s = d = i - E;
        }
        g_src[i] = s;
        g_dst[i] = d;
        atomicAdd(&g_deg[d], 1);
        if (i < N) g_batch[i] = load_idx(batch, i, is64, NGRAPH);
    }
}

// ---------------- hierarchical scan ----------------
__global__ void scan_block(int N)
{
    int t = threadIdx.x;
    int i = blockIdx.x * SCAN_B + t;
    int v = (i < N) ? g_deg[i] : 0;
    int x = v;
#pragma unroll
    for (int o = 1; o < 32; o <<= 1) {
        int y = __shfl_up_sync(0xFFFFFFFFu, x, o);
        if ((t & 31) >= o) x += y;
    }
    __shared__ int wsum[32];
    if ((t & 31) == 31) wsum[t >> 5] = x;
    __syncthreads();
    if (t < 32) {
        int s = wsum[t];
#pragma unroll
        for (int o = 1; o < 32; o <<= 1) {
            int y = __shfl_up_sync(0xFFFFFFFFu, s, o);
            if (t >= o) s += y;
        }
        wsum[t] = s;
    }
    __syncthreads();
    int base = (t >= 32) ? wsum[(t >> 5) - 1] : 0;
    int incl = x + base;
    if (i < N) g_rowstart[i] = incl - v;
    if (t == SCAN_B - 1) g_bsum[blockIdx.x] = incl;
}

__global__ void scan_partials(int nb)
{
    if (threadIdx.x == 0) {
        int s = 0;
        for (int b = 0; b < nb; b++) { int v = g_bsum[b]; g_bsum[b] = s; s += v; }
        g_total = s;
    }
}

__global__ void scan_add(int N)
{
    int i = blockIdx.x * blockDim.x + threadIdx.x;
    if (i < N) {
        int r = g_rowstart[i] + g_bsum[i >> 10];
        g_rowstart[i] = r;
        g_cursor[i] = r;
    }
    if (i == 0) g_rowstart[N] = g_total;
}

__global__ void scatter_kernel(int ET)
{
    for (int i = blockIdx.x * blockDim.x + threadIdx.x; i < ET;
         i += gridDim.x * blockDim.x) {
        int d = g_dst[i];
        int pos = atomicAdd(&g_cursor[d], 1);
        g_csr[pos] = g_src[i];
    }
}

// ---------------- fused GEMM (128x64 tiles, 4 blocks/SM, BK=16) ----------------
// blockIdx.y: bit1 = side (0=Wl->fp16 xl, 1=Wr->fp32 xr), bit0 = column half (0..1)
__global__ __launch_bounds__(256, 4)
void gemm_nt(const float* __restrict__ A,
             const float* __restrict__ Wl, const float* __restrict__ Wr,
             const float* __restrict__ bl, const float* __restrict__ br,
             __half* __restrict__ Cxl, float* __restrict__ Cxr, int M, int K)
{
    __shared__ float As[16][128];
    __shared__ float Ws[16][64];

    int side = blockIdx.y >> 1;
    int half = blockIdx.y & 1;
    const float* W  = side ? Wr : Wl;
    const float* bv = side ? br : bl;

    int m0 = blockIdx.x * 128;
    int t = threadIdx.x;
    int tx = t & 15;              // col micro: 4 cols each
    int ty = t >> 4;              // row micro: 8 rows each
    int lrow = t >> 1;            // A-load row 0..127
    int lseg = (t & 1) * 8;       // A-load k-seg 0 or 8
    int wrow = t >> 2;            // W-load row 0..63
    int wseg = (t & 3) * 4;       // W-load k-seg 0,4,8,12

    float acc[8][4];
#pragma unroll
    for (int i = 0; i < 8; i++)
#pragma unroll
        for (int j = 0; j < 4; j++) acc[i][j] = 0.f;

    int ar = m0 + lrow;
    int arc = ar < M ? ar : M - 1;
    const float* Arow = A + (size_t)arc * K;
    const float* Wrow = W + (size_t)(half * 64 + wrow) * K;

    float4 a0 = *(const float4*)(Arow + lseg);
    float4 a1 = *(const float4*)(Arow + lseg + 4);
    float4 w0 = *(const float4*)(Wrow + wseg);

    for (int k0 = 0; k0 < K; k0 += 16) {
        As[lseg + 0][lrow] = a0.x; As[lseg + 1][lrow] = a0.y;
        As[lseg + 2][lrow] = a0.z; As[lseg + 3][lrow] = a0.w;
        As[lseg + 4][lrow] = a1.x; As[lseg + 5][lrow] = a1.y;
        As[lseg + 6][lrow] = a1.z; As[lseg + 7][lrow] = a1.w;
        Ws[wseg + 0][wrow] = w0.x; Ws[wseg + 1][wrow] = w0.y;
        Ws[wseg + 2][wrow] = w0.z; Ws[wseg + 3][wrow] = w0.w;
        __syncthreads();

        if (k0 + 16 < K) {
            a0 = *(const float4*)(Arow + k0 + 16 + lseg);
            a1 = *(const float4*)(Arow + k0 + 16 + lseg + 4);
            w0 = *(const float4*)(Wrow + k0 + 16 + wseg);
        }

#pragma unroll
        for (int kk = 0; kk < 16; kk++) {
            float4 ra0 = *(const float4*)&As[kk][ty * 8];
            float4 ra1 = *(const float4*)&As[kk][ty * 8 + 4];
            float4 rw0 = *(const float4*)&Ws[kk][tx * 4];
            float ra[8] = {ra0.x, ra0.y, ra0.z, ra0.w, ra1.x, ra1.y, ra1.z, ra1.w};
            float rw[4] = {rw0.x, rw0.y, rw0.z, rw0.w};
#pragma unroll
            for (int i = 0; i < 8; i++)
#pragma unroll
                for (int j = 0; j < 4; j++) acc[i][j] += ra[i] * rw[j];
        }
        __syncthreads();
    }

    int colbase = half * 64 + tx * 4;
    float bias[4];
#pragma unroll
    for (int j = 0; j < 4; j++) bias[j] = bv[colbase + j];

    if (side == 0) {
        // fp16 xl output: 4 halves = 8B store
#pragma unroll
        for (int i = 0; i < 8; i++) {
            int row = m0 + ty * 8 + i;
            if (row < M) {
                union { __half2 h[2]; uint2 u; } pack;
                pack.h[0] = __floats2half2_rn(acc[i][0] + bias[0], acc[i][1] + bias[1]);
                pack.h[1] = __floats2half2_rn(acc[i][2] + bias[2], acc[i][3] + bias[3]);
                *(uint2*)&Cxl[(size_t)row * HID + colbase] = pack.u;
            }
        }
    } else {
        // fp32 xr output
#pragma unroll
        for (int i = 0; i < 8; i++) {
            int row = m0 + ty * 8 + i;
            if (row < M) {
                *(float4*)&Cxr[(size_t)row * HID + colbase] =
                    make_float4(acc[i][0] + bias[0], acc[i][1] + bias[1],
                                acc[i][2] + bias[2], acc[i][3] + bias[3]);
            }
        }
    }
}

// ---------------- fused node kernel (4-deep prefetch, fp16 xl) ----------------
__device__ __forceinline__ float lrelu(float x) {
    return fmaxf(x, 0.f) + 0.2f * fminf(x, 0.f);
}

__device__ __forceinline__ float4 xl_load(int node, int lane)
{
    union { uint2 u; __half2 h[2]; } raw;
    raw.u = *(const uint2*)&g_xlh[(size_t)node * HID + 4 * lane];
    float2 f0 = __half22float2(raw.h[0]);
    float2 f1 = __half22float2(raw.h[1]);
    return make_float4(f0.x, f0.y, f1.x, f1.y);
}

__global__ void node_gather(const float* __restrict__ att, const float* __restrict__ bias,
                            float* __restrict__ out, int N, int dorelu)
{
    int v = (int)((blockIdx.x * (unsigned)blockDim.x + threadIdx.x) >> 5);
    int lane = threadIdx.x & 31;
    if (v >= N) return;

    float4 a4  = ((const float4*)att)[lane];
    float4 xr4 = *(const float4*)&g_xr[(size_t)v * HID + 4 * lane];

    int beg = g_rowstart[v];
    int end = g_rowstart[v + 1];          // deg >= 1 (self-loop guaranteed)
    int deg = end - beg;

    float4 acc = make_float4(0.f, 0.f, 0.f, 0.f);
    float den = 0.f;

    float4 b0, b1, b2, b3;
    {
        int s0 = g_csr[beg];
        int s1 = g_csr[1 < deg ? beg + 1 : beg];
        int s2 = g_csr[2 < deg ? beg + 2 : beg];
        int s3 = g_csr[3 < deg ? beg + 3 : beg];
        b0 = xl_load(s0, lane);
        b1 = xl_load(s1, lane);
        b2 = xl_load(s2, lane);
        b3 = xl_load(s3, lane);
    }

#define NG_STEP(BUF, PF)                                                        \
    {                                                                           \
        float4 xl = BUF;                                                        \
        int pf = (PF);                                                          \
        if (pf < end) {                                                         \
            int sn = g_csr[pf];                                                 \
            BUF = xl_load(sn, lane);                                            \
        }                                                                       \
        float p = lrelu(xl.x + xr4.x) * a4.x                                    \
                + lrelu(xl.y + xr4.y) * a4.y                                    \
                + lrelu(xl.z + xr4.z) * a4.z                                    \
                + lrelu(xl.w + xr4.w) * a4.w;                                   \
        p += __shfl_xor_sync(0xFFFFFFFFu, p, 1);                                \
        p += __shfl_xor_sync(0xFFFFFFFFu, p, 2);                                \
        p += __shfl_xor_sync(0xFFFFFFFFu, p, 4);                                \
        float w = __expf(p);                                                    \
        acc.x += w * xl.x; acc.y += w * xl.y;                                   \
        acc.z += w * xl.z; acc.w += w * xl.w;                                   \
        den += w;                                                               \
    }

    int n4 = (deg >> 2) << 2;
    int e = beg;
    for (; e < beg + n4; e += 4) {
        NG_STEP(b0, e + 4)
        NG_STEP(b1, e + 5)
        NG_STEP(b2, e + 6)
        NG_STEP(b3, e + 7)
    }
    int rem = end - e;
    if (rem > 0) NG_STEP(b0, end)
    if (rem > 1) NG_STEP(b1, end)
    if (rem > 2) NG_STEP(b2, end)
#undef NG_STEP

    float inv = 1.f / (den + 1e-16f);
    const float4 b4 = ((const float4*)bias)[lane];
    float4 o = make_float4(acc.x * inv + b4.x, acc.y * inv + b4.y,
                           acc.z * inv + b4.z, acc.w * inv + b4.w);
    if (dorelu) {
        o.x = fmaxf(o.x, 0.f); o.y = fmaxf(o.y, 0.f);
        o.z = fmaxf(o.z, 0.f); o.w = fmaxf(o.w, 0.f);
    }
    *(float4*)&out[(size_t)v * HID + 4 * lane] = o;
}

// ---------------- pool / head ----------------
__global__ void init_pool()
{
    int i = blockIdx.x * blockDim.x + threadIdx.x;
    if (i < NGRAPH * HID) g_pool[i] = 0.f;
    if (i < NGRAPH) g_cnt[i] = 0.f;
}

__global__ void pool_kernel(const float* __restrict__ h, int N)
{
    int j = threadIdx.x;                // 128
    int n0 = blockIdx.x * 128;
    if (n0 >= N) return;
    int nend = min(n0 + 128, N);
    int cur = g_batch[n0];
    float acc = 0.f, c = 0.f;
    for (int n = n0; n < nend; n++) {
        int g = g_batch[n];
        if (g != cur) {
            atomicAdd(&g_pool[cur * HID + j], acc);
            if (j == 0) atomicAdd(&g_cnt[cur], c);
            acc = 0.f; c = 0.f; cur = g;
        }
        acc += h[(size_t)n * HID + j];
        c += 1.f;
    }
    atomicAdd(&g_pool[cur * HID + j], acc);
    if (j == 0) atomicAdd(&g_cnt[cur], c);
}

__global__ void head_kernel(const float* __restrict__ Wlin, const float* __restrict__ blin,
                            float* __restrict__ out)
{
    int g = threadIdx.x;
    if (g >= NGRAPH) return;
    float cnt = fmaxf(g_cnt[g], 1.f);
    float s = 0.f;
#pragma unroll 4
    for (int k = 0; k < HID; k++) s += g_pool[g * HID + k] * Wlin[k];
    out[g] = s / cnt + blin[0];
}

// ---------------- launch ----------------
extern "C" void kernel_launch(void* const* d_in, const int* in_sizes, int n_in,
                              void* d_out, int out_size)
{
    const float* x     = (const float*)d_in[0];
    const void*  ei    = d_in[1];
    const void*  batch = d_in[2];
    const float* Wl1  = (const float*)d_in[3];
    const float* bl1  = (const float*)d_in[4];
    const float* Wr1  = (const float*)d_in[5];
    const float* br1  = (const float*)d_in[6];
    const float* att1 = (const float*)d_in[7];
    const float* bias1= (const float*)d_in[8];
    const float* Wl2  = (const float*)d_in[9];
    const float* bl2  = (const float*)d_in[10];
    const float* Wr2  = (const float*)d_in[11];
    const float* br2  = (const float*)d_in[12];
    const float* att2 = (const float*)d_in[13];
    const float* bias2= (const float*)d_in[14];
    const float* Wlin = (const float*)d_in[15];
    const float* blin = (const float*)d_in[16];

    int hidden = in_sizes[4];              // 128
    int Fin    = in_sizes[3] / hidden;     // 256
    int N      = in_sizes[0] / Fin;        // 50000
    int E      = in_sizes[1] / 2;          // 1600000
    int ET     = E + N;
    int nb     = (N + SCAN_B - 1) / SCAN_B;

    __half* xlh;
    float *xr, *h1, *h2;
    cudaGetSymbolAddress((void**)&xlh, g_xlh);
    cudaGetSymbolAddress((void**)&xr, g_xr);
    cudaGetSymbolAddress((void**)&h1, g_h1);
    cudaGetSymbolAddress((void**)&h2, g_h2);

    int nodeBlocks = (int)(((long long)N * 32 + 255) / 256);
    dim3 gemmGrid((N + 127) / 128, 4);

    static cudaStream_t s_side = nullptr;
    static cudaEvent_t ev_fork = nullptr, ev_csr = nullptr;
    if (s_side == nullptr) {
        cudaStreamCreateWithFlags(&s_side, cudaStreamNonBlocking);
        cudaEventCreateWithFlags(&ev_fork, cudaEventDisableTiming);
        cudaEventCreateWithFlags(&ev_csr, cudaEventDisableTiming);
    }

    // ---- fork: CSR build on side stream, gemm1 on main ----
    cudaEventRecord(ev_fork, 0);
    cudaStreamWaitEvent(s_side, ev_fork, 0);

    detect_kernel<<<1, 32, 0, s_side>>>((const unsigned*)ei);
    zero_deg<<<(N + 255) / 256, 256, 0, s_side>>>(N);
    convert_kernel<<<2048, 256, 0, s_side>>>(ei, batch, E, N);
    scan_block<<<nb, SCAN_B, 0, s_side>>>(N);
    scan_partials<<<1, 32, 0, s_side>>>(nb);
    scan_add<<<(N + 255) / 256, 256, 0, s_side>>>(N);
    scatter_kernel<<<2048, 256, 0, s_side>>>(ET);
    cudaEventRecord(ev_csr, s_side);

    gemm_nt<<<gemmGrid, 256>>>(x, Wl1, Wr1, bl1, br1, xlh, xr, N, Fin);
    cudaStreamWaitEvent(0, ev_csr, 0);

    // ---- layer 1 ----
    node_gather<<<nodeBlocks, 256>>>(att1, bias1, h1, N, 1);

    // ---- layer 2 ----
    gemm_nt<<<gemmGrid, 256>>>(h1, Wl2, Wr2, bl2, br2, xlh, xr, N, hidden);
    node_gather<<<nodeBlocks, 256>>>(att2, bias2, h2, N, 0);

    // ---- pool + head ----
    init_pool<<<(NGRAPH * HID + 255) / 256, 256>>>();
    pool_kernel<<<(N + 127) / 128, 128>>>(h2, N);
    head_kernel<<<1, 64>>>(Wlin, blin, (float*)d_out);
}

// round 15
// speedup vs baseline: 1.2029x; 1.2029x over previous
#include <cuda_runtime.h>
#include <cuda_fp16.h>

// ---------------- problem constants ----------------
#define MAXN 50000
#define MAXE 1600000
#define HID 128
#define HEADS 4
#define NGRAPH 64
#define SCAN_B 1024

// ---------------- scratch (static device memory; no allocations) ----------------
__device__ __align__(256) __half g_xlh[(size_t)MAXN * HID];  // fp16 xl table (gathered per edge)
__device__ __align__(256) float  g_xr [(size_t)MAXN * HID];  // fp32 xr table (read once per node)
__device__ __align__(256) float  g_h1[(size_t)MAXN * HID];
__device__ __align__(256) int    g_src[MAXE + MAXN];
__device__ __align__(256) int    g_dst[MAXE + MAXN];
__device__ __align__(256) int    g_csr[MAXE + MAXN];
__device__ __align__(256) int    g_deg[MAXN];
__device__ __align__(256) int    g_rowstart[MAXN + 1];
__device__ __align__(256) int    g_cursor[MAXN];
__device__ __align__(256) int    g_batch[MAXN];
__device__ int   g_bsum[(MAXN + SCAN_B - 1) / SCAN_B];
__device__ int   g_total;
__device__ __align__(256) float g_pool[NGRAPH * HID];
__device__ float g_cnt[NGRAPH];
__device__ int   g_is64;

// ---------------- dtype detect ----------------
__global__ void detect_kernel(const unsigned* __restrict__ p)
{
    if (threadIdx.x == 0) {
        unsigned o = 0;
        for (int i = 0; i < 256; i++) o |= p[2 * i + 1];
        g_is64 = (o == 0) ? 1 : 0;
    }
}

__device__ __forceinline__ int load_idx(const void* p, int i, int is64, int N)
{
    long long v = is64 ? ((const long long*)p)[i] : (long long)((const int*)p)[i];
    int r = (int)v;
    return r < 0 ? 0 : (r >= N ? N - 1 : r);
}

// zero deg + pool + cnt (runs before convert on side stream)
__global__ void zero_deg(int N)
{
    int i = blockIdx.x * blockDim.x + threadIdx.x;
    if (i < N) g_deg[i] = 0;
    if (i < NGRAPH * HID) g_pool[i] = 0.f;
    if (i < NGRAPH) g_cnt[i] = 0.f;
}

// canonicalize edges + batch, degree histogram, per-graph node counts
__global__ void convert_kernel(const void* __restrict__ ei, const void* __restrict__ batch,
                               int E, int N)
{
    int is64 = g_is64;
    int ET = E + N;
    for (int i = blockIdx.x * blockDim.x + threadIdx.x; i < ET;
         i += gridDim.x * blockDim.x) {
        int s, d;
        if (i < E) {
            s = load_idx(ei, i, is64, N);
            d = load_idx(ei, E + i, is64, N);
        } else {
            s = d = i - E;
        }
        g_src[i] = s;
        g_dst[i] = d;
        atomicAdd(&g_deg[d], 1);
        if (i < N) {
            int b = load_idx(batch, i, is64, NGRAPH);
            g_batch[i] = b;
            atomicAdd(&g_cnt[b], 1.f);
        }
    }
}

// ---------------- hierarchical scan ----------------
__global__ void scan_block(int N)
{
    int t = threadIdx.x;
    int i = blockIdx.x * SCAN_B + t;
    int v = (i < N) ? g_deg[i] : 0;
    int x = v;
#pragma unroll
    for (int o = 1; o < 32; o <<= 1) {
        int y = __shfl_up_sync(0xFFFFFFFFu, x, o);
        if ((t & 31) >= o) x += y;
    }
    __shared__ int wsum[32];
    if ((t & 31) == 31) wsum[t >> 5] = x;
    __syncthreads();
    if (t < 32) {
        int s = wsum[t];
#pragma unroll
        for (int o = 1; o < 32; o <<= 1) {
            int y = __shfl_up_sync(0xFFFFFFFFu, s, o);
            if (t >= o) s += y;
        }
        wsum[t] = s;
    }
    __syncthreads();
    int base = (t >= 32) ? wsum[(t >> 5) - 1] : 0;
    int incl = x + base;
    if (i < N) g_rowstart[i] = incl - v;
    if (t == SCAN_B - 1) g_bsum[blockIdx.x] = incl;
}

__global__ void scan_partials(int nb)
{
    if (threadIdx.x == 0) {
        int s = 0;
        for (int b = 0; b < nb; b++) { int v = g_bsum[b]; g_bsum[b] = s; s += v; }
        g_total = s;
    }
}

__global__ void scan_add(int N)
{
    int i = blockIdx.x * blockDim.x + threadIdx.x;
    if (i < N) {
        int r = g_rowstart[i] + g_bsum[i >> 10];
        g_rowstart[i] = r;
        g_cursor[i] = r;
    }
    if (i == 0) g_rowstart[N] = g_total;
}

__global__ void scatter_kernel(int ET)
{
    for (int i = blockIdx.x * blockDim.x + threadIdx.x; i < ET;
         i += gridDim.x * blockDim.x) {
        int d = g_dst[i];
        int pos = atomicAdd(&g_cursor[d], 1);
        g_csr[pos] = g_src[i];
    }
}

// ---------------- fused GEMM (R13: single-buffer, BK=16, register prefetch) ----------
// blockIdx.y==0: xl pass -> writes fp16 g_xlh ; blockIdx.y==1: xr pass -> writes fp32 g_xr
__global__ __launch_bounds__(256, 2)
void gemm_nt(const float* __restrict__ A,
             const float* __restrict__ Wl, const float* __restrict__ Wr,
             const float* __restrict__ bl, const float* __restrict__ br,
             __half* __restrict__ Cxl, float* __restrict__ Cxr, int M, int K)
{
    __shared__ float As[16][128];
    __shared__ float Ws[16][128];
    const float* W  = blockIdx.y ? Wr : Wl;
    const float* bv = blockIdx.y ? br : bl;

    int m0 = blockIdx.x * 128;
    int t = threadIdx.x;
    int tx = t & 15;
    int ty = t >> 4;
    int lrow = t >> 1;
    int lseg = (t & 1) * 8;

    float acc[8][8];
#pragma unroll
    for (int i = 0; i < 8; i++)
#pragma unroll
        for (int j = 0; j < 8; j++) acc[i][j] = 0.f;

    int ar = m0 + lrow;
    int arc = ar < M ? ar : M - 1;
    const float* Arow = A + (size_t)arc * K;
    const float* Wrow = W + (size_t)lrow * K;

    float4 a0 = *(const float4*)(Arow + lseg);
    float4 a1 = *(const float4*)(Arow + lseg + 4);
    float4 w0 = *(const float4*)(Wrow + lseg);
    float4 w1 = *(const float4*)(Wrow + lseg + 4);

    for (int k0 = 0; k0 < K; k0 += 16) {
        As[lseg + 0][lrow] = a0.x; As[lseg + 1][lrow] = a0.y;
        As[lseg + 2][lrow] = a0.z; As[lseg + 3][lrow] = a0.w;
        As[lseg + 4][lrow] = a1.x; As[lseg + 5][lrow] = a1.y;
        As[lseg + 6][lrow] = a1.z; As[lseg + 7][lrow] = a1.w;
        Ws[lseg + 0][lrow] = w0.x; Ws[lseg + 1][lrow] = w0.y;
        Ws[lseg + 2][lrow] = w0.z; Ws[lseg + 3][lrow] = w0.w;
        Ws[lseg + 4][lrow] = w1.x; Ws[lseg + 5][lrow] = w1.y;
        Ws[lseg + 6][lrow] = w1.z; Ws[lseg + 7][lrow] = w1.w;
        __syncthreads();

        if (k0 + 16 < K) {
            a0 = *(const float4*)(Arow + k0 + 16 + lseg);
            a1 = *(const float4*)(Arow + k0 + 16 + lseg + 4);
            w0 = *(const float4*)(Wrow + k0 + 16 + lseg);
            w1 = *(const float4*)(Wrow + k0 + 16 + lseg + 4);
        }

#pragma unroll
        for (int kk = 0; kk < 16; kk++) {
            float4 ra0 = *(const float4*)&As[kk][ty * 8];
            float4 ra1 = *(const float4*)&As[kk][ty * 8 + 4];
            float4 rw0 = *(const float4*)&Ws[kk][tx * 8];
            float4 rw1 = *(const float4*)&Ws[kk][tx * 8 + 4];
            float ra[8] = {ra0.x, ra0.y, ra0.z, ra0.w, ra1.x, ra1.y, ra1.z, ra1.w};
            float rw[8] = {rw0.x, rw0.y, rw0.z, rw0.w, rw1.x, rw1.y, rw1.z, rw1.w};
#pragma unroll
            for (int i = 0; i < 8; i++)
#pragma unroll
                for (int j = 0; j < 8; j++) acc[i][j] += ra[i] * rw[j];
        }
        __syncthreads();
    }

    float bias[8];
#pragma unroll
    for (int j = 0; j < 8; j++) bias[j] = bv[tx * 8 + j];

    if (blockIdx.y == 0) {
#pragma unroll
        for (int i = 0; i < 8; i++) {
            int row = m0 + ty * 8 + i;
            if (row < M) {
                union { __half2 h[4]; uint4 u; } pack;
                pack.h[0] = __floats2half2_rn(acc[i][0] + bias[0], acc[i][1] + bias[1]);
                pack.h[1] = __floats2half2_rn(acc[i][2] + bias[2], acc[i][3] + bias[3]);
                pack.h[2] = __floats2half2_rn(acc[i][4] + bias[4], acc[i][5] + bias[5]);
                pack.h[3] = __floats2half2_rn(acc[i][6] + bias[6], acc[i][7] + bias[7]);
                *(uint4*)&Cxl[(size_t)row * HID + tx * 8] = pack.u;
            }
        }
    } else {
#pragma unroll
        for (int i = 0; i < 8; i++) {
            int row = m0 + ty * 8 + i;
            if (row < M) {
                float* dst = Cxr + (size_t)row * HID + tx * 8;
                *(float4*)(dst + 0) = make_float4(acc[i][0] + bias[0], acc[i][1] + bias[1],
                                                  acc[i][2] + bias[2], acc[i][3] + bias[3]);
                *(float4*)(dst + 4) = make_float4(acc[i][4] + bias[4], acc[i][5] + bias[5],
                                                  acc[i][6] + bias[6], acc[i][7] + bias[7]);
            }
        }
    }
}

// ---------------- fused node kernel (4-deep prefetch, fp16 xl) ----------------
// mode 0: write out; mode 1: write out + relu; mode 2: pool-atomic (no out write)
__device__ __forceinline__ float lrelu(float x) {
    return fmaxf(x, 0.f) + 0.2f * fminf(x, 0.f);
}

__device__ __forceinline__ float4 xl_load(int node, int lane)
{
    union { uint2 u; __half2 h[2]; } raw;
    raw.u = *(const uint2*)&g_xlh[(size_t)node * HID + 4 * lane];
    float2 f0 = __half22float2(raw.h[0]);
    float2 f1 = __half22float2(raw.h[1]);
    return make_float4(f0.x, f0.y, f1.x, f1.y);
}

__global__ void node_gather(const float* __restrict__ att, const float* __restrict__ bias,
                            float* __restrict__ out, int N, int mode)
{
    int v = (int)((blockIdx.x * (unsigned)blockDim.x + threadIdx.x) >> 5);
    int lane = threadIdx.x & 31;
    if (v >= N) return;

    float4 a4  = ((const float4*)att)[lane];
    float4 xr4 = *(const float4*)&g_xr[(size_t)v * HID + 4 * lane];

    int beg = g_rowstart[v];
    int end = g_rowstart[v + 1];          // deg >= 1 (self-loop guaranteed)
    int deg = end - beg;

    float4 acc = make_float4(0.f, 0.f, 0.f, 0.f);
    float den = 0.f;

    float4 b0, b1, b2, b3;
    {
        int s0 = g_csr[beg];
        int s1 = g_csr[1 < deg ? beg + 1 : beg];
        int s2 = g_csr[2 < deg ? beg + 2 : beg];
        int s3 = g_csr[3 < deg ? beg + 3 : beg];
        b0 = xl_load(s0, lane);
        b1 = xl_load(s1, lane);
        b2 = xl_load(s2, lane);
        b3 = xl_load(s3, lane);
    }

#define NG_STEP(BUF, PF)                                                        \
    {                                                                           \
        float4 xl = BUF;                                                        \
        int pf = (PF);                                                          \
        if (pf < end) {                                                         \
            int sn = g_csr[pf];                                                 \
            BUF = xl_load(sn, lane);                                            \
        }                                                                       \
        float p = lrelu(xl.x + xr4.x) * a4.x                                    \
                + lrelu(xl.y + xr4.y) * a4.y                                    \
                + lrelu(xl.z + xr4.z) * a4.z                                    \
                + lrelu(xl.w + xr4.w) * a4.w;                                   \
        p += __shfl_xor_sync(0xFFFFFFFFu, p, 1);                                \
        p += __shfl_xor_sync(0xFFFFFFFFu, p, 2);                                \
        p += __shfl_xor_sync(0xFFFFFFFFu, p, 4);                                \
        float w = __expf(p);                                                    \
        acc.x += w * xl.x; acc.y += w * xl.y;                                   \
        acc.z += w * xl.z; acc.w += w * xl.w;                                   \
        den += w;                                                               \
    }

    int n4 = (deg >> 2) << 2;
    int e = beg;
    for (; e < beg + n4; e += 4) {
        NG_STEP(b0, e + 4)
        NG_STEP(b1, e + 5)
        NG_STEP(b2, e + 6)
        NG_STEP(b3, e + 7)
    }
    int rem = end - e;
    if (rem > 0) NG_STEP(b0, end)
    if (rem > 1) NG_STEP(b1, end)
    if (rem > 2) NG_STEP(b2, end)
#undef NG_STEP

    float inv = 1.f / (den + 1e-16f);
    const float4 b4 = ((const float4*)bias)[lane];
    float4 o = make_float4(acc.x * inv + b4.x, acc.y * inv + b4.y,
                           acc.z * inv + b4.z, acc.w * inv + b4.w);

    if (mode == 2) {
        // fused global mean pool: accumulate into g_pool[batch[v]]
        int g = g_batch[v];
        float* p = &g_pool[g * HID + 4 * lane];
        asm volatile("red.global.add.v4.f32 [%0], {%1,%2,%3,%4};"
                     :: "l"(p), "f"(o.x), "f"(o.y), "f"(o.z), "f"(o.w)
                     : "memory");
        return;
    }
    if (mode == 1) {
        o.x = fmaxf(o.x, 0.f); o.y = fmaxf(o.y, 0.f);
        o.z = fmaxf(o.z, 0.f); o.w = fmaxf(o.w, 0.f);
    }
    *(float4*)&out[(size_t)v * HID + 4 * lane] = o;
}

// ---------------- head ----------------
__global__ void head_kernel(const float* __restrict__ Wlin, const float* __restrict__ blin,
                            float* __restrict__ out)
{
    int g = threadIdx.x;
    if (g >= NGRAPH) return;
    float cnt = fmaxf(g_cnt[g], 1.f);
    float s = 0.f;
#pragma unroll 4
    for (int k = 0; k < HID; k++) s += g_pool[g * HID + k] * Wlin[k];
    out[g] = s / cnt + blin[0];
}

// ---------------- launch ----------------
extern "C" void kernel_launch(void* const* d_in, const int* in_sizes, int n_in,
                              void* d_out, int out_size)
{
    const float* x     = (const float*)d_in[0];
    const void*  ei    = d_in[1];
    const void*  batch = d_in[2];
    const float* Wl1  = (const float*)d_in[3];
    const float* bl1  = (const float*)d_in[4];
    const float* Wr1  = (const float*)d_in[5];
    const float* br1  = (const float*)d_in[6];
    const float* att1 = (const float*)d_in[7];
    const float* bias1= (const float*)d_in[8];
    const float* Wl2  = (const float*)d_in[9];
    const float* bl2  = (const float*)d_in[10];
    const float* Wr2  = (const float*)d_in[11];
    const float* br2  = (const float*)d_in[12];
    const float* att2 = (const float*)d_in[13];
    const float* bias2= (const float*)d_in[14];
    const float* Wlin = (const float*)d_in[15];
    const float* blin = (const float*)d_in[16];

    int hidden = in_sizes[4];              // 128
    int Fin    = in_sizes[3] / hidden;     // 256
    int N      = in_sizes[0] / Fin;        // 50000
    int E      = in_sizes[1] / 2;          // 1600000
    int ET     = E + N;
    int nb     = (N + SCAN_B - 1) / SCAN_B;

    __half* xlh;
    float *xr, *h1;
    cudaGetSymbolAddress((void**)&xlh, g_xlh);
    cudaGetSymbolAddress((void**)&xr, g_xr);
    cudaGetSymbolAddress((void**)&h1, g_h1);

    int nodeBlocks = (int)(((long long)N * 32 + 255) / 256);
    dim3 gemmGrid((N + 127) / 128, 2);

    static cudaStream_t s_side = nullptr;
    static cudaEvent_t ev_fork = nullptr, ev_csr = nullptr;
    if (s_side == nullptr) {
        cudaStreamCreateWithFlags(&s_side, cudaStreamNonBlocking);
        cudaEventCreateWithFlags(&ev_fork, cudaEventDisableTiming);
        cudaEventCreateWithFlags(&ev_csr, cudaEventDisableTiming);
    }

    // ---- fork: CSR build (+ pool/cnt init) on side stream, gemm1 on main ----
    cudaEventRecord(ev_fork, 0);
    cudaStreamWaitEvent(s_side, ev_fork, 0);

    detect_kernel<<<1, 32, 0, s_side>>>((const unsigned*)ei);
    zero_deg<<<(N + 255) / 256, 256, 0, s_side>>>(N);
    convert_kernel<<<2048, 256, 0, s_side>>>(ei, batch, E, N);
    scan_block<<<nb, SCAN_B, 0, s_side>>>(N);
    scan_partials<<<1, 32, 0, s_side>>>(nb);
    scan_add<<<(N + 255) / 256, 256, 0, s_side>>>(N);
    scatter_kernel<<<2048, 256, 0, s_side>>>(ET);
    cudaEventRecord(ev_csr, s_side);

    gemm_nt<<<gemmGrid, 256>>>(x, Wl1, Wr1, bl1, br1, xlh, xr, N, Fin);
    cudaStreamWaitEvent(0, ev_csr, 0);

    // ---- layer 1 (write h1 + relu) ----
    node_gather<<<nodeBlocks, 256>>>(att1, bias1, h1, N, 1);

    // ---- layer 2 (fused pooling; no h2) ----
    gemm_nt<<<gemmGrid, 256>>>(h1, Wl2, Wr2, bl2, br2, xlh, xr, N, hidden);
    node_gather<<<nodeBlocks, 256>>>(att2, bias2, h1 /*unused*/, N, 2);

    // ---- head ----
    head_kernel<<<1, 64>>>(Wlin, blin, (float*)d_out);
}

// round 16
// speedup vs baseline: 1.3512x; 1.1233x over previous
#include <cuda_runtime.h>
#include <cuda_fp16.h>

// ---------------- problem constants ----------------
#define MAXN 50000
#define MAXE 1600000
#define HID 128
#define HEADS 4
#define NGRAPH 64
#define SCAN_B 1024

// ---------------- scratch (static device memory; no allocations) ----------------
__device__ __align__(256) __half g_xlh[(size_t)MAXN * HID];  // fp16 xl table (gathered per edge)
__device__ __align__(256) float  g_xr [(size_t)MAXN * HID];  // fp32 xr table (read once per node)
__device__ __align__(256) float  g_h1[(size_t)MAXN * HID];
__device__ __align__(256) int    g_src[MAXE + MAXN];
__device__ __align__(256) int    g_dst[MAXE + MAXN];
__device__ __align__(256) int    g_csr[MAXE + MAXN];
__device__ __align__(256) int    g_deg[MAXN];
__device__ __align__(256) int    g_rowstart[MAXN + 1];
__device__ __align__(256) int    g_cursor[MAXN];
__device__ __align__(256) int    g_batch[MAXN];
__device__ int   g_bsum[(MAXN + SCAN_B - 1) / SCAN_B];
__device__ int   g_total;
__device__ __align__(256) float g_pool[NGRAPH * HID];
__device__ float g_cnt[NGRAPH];
__device__ int   g_is64;

// ---------------- dtype detect ----------------
__global__ void detect_kernel(const unsigned* __restrict__ p)
{
    if (threadIdx.x == 0) {
        unsigned o = 0;
        for (int i = 0; i < 256; i++) o |= p[2 * i + 1];
        g_is64 = (o == 0) ? 1 : 0;
    }
}

__device__ __forceinline__ int load_idx(const void* p, int i, int is64, int N)
{
    long long v = is64 ? ((const long long*)p)[i] : (long long)((const int*)p)[i];
    int r = (int)v;
    return r < 0 ? 0 : (r >= N ? N - 1 : r);
}

// zero deg + pool + cnt (runs before convert on side stream)
__global__ void zero_deg(int N)
{
    int i = blockIdx.x * blockDim.x + threadIdx.x;
    if (i < N) g_deg[i] = 0;
    if (i < NGRAPH * HID) g_pool[i] = 0.f;
    if (i < NGRAPH) g_cnt[i] = 0.f;
}

// canonicalize edges + batch, degree histogram, per-graph node counts
__global__ void convert_kernel(const void* __restrict__ ei, const void* __restrict__ batch,
                               int E, int N)
{
    int is64 = g_is64;
    int ET = E + N;
    for (int i = blockIdx.x * blockDim.x + threadIdx.x; i < ET;
         i += gridDim.x * blockDim.x) {
        int s, d;
        if (i < E) {
            s = load_idx(ei, i, is64, N);
            d = load_idx(ei, E + i, is64, N);
        } else {
            s = d = i - E;
        }
        g_src[i] = s;
        g_dst[i] = d;
        atomicAdd(&g_deg[d], 1);
        if (i < N) {
            int b = load_idx(batch, i, is64, NGRAPH);
            g_batch[i] = b;
            atomicAdd(&g_cnt[b], 1.f);
        }
    }
}

// ---------------- hierarchical scan ----------------
__global__ void scan_block(int N)
{
    int t = threadIdx.x;
    int i = blockIdx.x * SCAN_B + t;
    int v = (i < N) ? g_deg[i] : 0;
    int x = v;
#pragma unroll
    for (int o = 1; o < 32; o <<= 1) {
        int y = __shfl_up_sync(0xFFFFFFFFu, x, o);
        if ((t & 31) >= o) x += y;
    }
    __shared__ int wsum[32];
    if ((t & 31) == 31) wsum[t >> 5] = x;
    __syncthreads();
    if (t < 32) {
        int s = wsum[t];
#pragma unroll
        for (int o = 1; o < 32; o <<= 1) {
            int y = __shfl_up_sync(0xFFFFFFFFu, s, o);
            if (t >= o) s += y;
        }
        wsum[t] = s;
    }
    __syncthreads();
    int base = (t >= 32) ? wsum[(t >> 5) - 1] : 0;
    int incl = x + base;
    if (i < N) g_rowstart[i] = incl - v;
    if (t == SCAN_B - 1) g_bsum[blockIdx.x] = incl;
}

__global__ void scan_partials(int nb)
{
    if (threadIdx.x == 0) {
        int s = 0;
        for (int b = 0; b < nb; b++) { int v = g_bsum[b]; g_bsum[b] = s; s += v; }
        g_total = s;
    }
}

__global__ void scan_add(int N)
{
    int i = blockIdx.x * blockDim.x + threadIdx.x;
    if (i < N) {
        int r = g_rowstart[i] + g_bsum[i >> 10];
        g_rowstart[i] = r;
        g_cursor[i] = r;
    }
    if (i == 0) g_rowstart[N] = g_total;
}

__global__ void scatter_kernel(int ET)
{
    for (int i = blockIdx.x * blockDim.x + threadIdx.x; i < ET;
         i += gridDim.x * blockDim.x) {
        int d = g_dst[i];
        int pos = atomicAdd(&g_cursor[d], 1);
        g_csr[pos] = g_src[i];
    }
}

// ---------------- fused GEMM: half2 k-packed HFMA2, BK=16, register prefetch ----------
// blockIdx.y==0: xl pass -> writes fp16 g_xlh ; blockIdx.y==1: xr pass -> writes fp32 g_xr
__global__ __launch_bounds__(256, 2)
void gemm_h2(const float* __restrict__ A,
             const float* __restrict__ Wl, const float* __restrict__ Wr,
             const float* __restrict__ bl, const float* __restrict__ br,
             __half* __restrict__ Cxl, float* __restrict__ Cxr, int M, int K)
{
    // k-pair-major tiles: [kp][row], kp covers 2 k values
    __shared__ __half2 As2[8][128];
    __shared__ __half2 Ws2[8][128];
    const float* W  = blockIdx.y ? Wr : Wl;
    const float* bv = blockIdx.y ? br : bl;

    int m0 = blockIdx.x * 128;
    int t = threadIdx.x;
    int tx = t & 15;
    int ty = t >> 4;
    int lrow = t >> 1;              // 0..127
    int lkp  = (t & 1) * 4;         // k-pair base 0 or 4 (covers k 0..7 / 8..15)

    __half2 acc2[8][8];
    __half2 hz = __float2half2_rn(0.f);
#pragma unroll
    for (int i = 0; i < 8; i++)
#pragma unroll
        for (int j = 0; j < 8; j++) acc2[i][j] = hz;

    int ar = m0 + lrow;
    int arc = ar < M ? ar : M - 1;
    const float* Arow = A + (size_t)arc * K;
    const float* Wrow = W + (size_t)lrow * K;

    float4 a0 = *(const float4*)(Arow + lkp * 2);
    float4 a1 = *(const float4*)(Arow + lkp * 2 + 4);
    float4 w0 = *(const float4*)(Wrow + lkp * 2);
    float4 w1 = *(const float4*)(Wrow + lkp * 2 + 4);

    for (int k0 = 0; k0 < K; k0 += 16) {
        As2[lkp + 0][lrow] = __floats2half2_rn(a0.x, a0.y);
        As2[lkp + 1][lrow] = __floats2half2_rn(a0.z, a0.w);
        As2[lkp + 2][lrow] = __floats2half2_rn(a1.x, a1.y);
        As2[lkp + 3][lrow] = __floats2half2_rn(a1.z, a1.w);
        Ws2[lkp + 0][lrow] = __floats2half2_rn(w0.x, w0.y);
        Ws2[lkp + 1][lrow] = __floats2half2_rn(w0.z, w0.w);
        Ws2[lkp + 2][lrow] = __floats2half2_rn(w1.x, w1.y);
        Ws2[lkp + 3][lrow] = __floats2half2_rn(w1.z, w1.w);
        __syncthreads();

        if (k0 + 16 < K) {
            a0 = *(const float4*)(Arow + k0 + 16 + lkp * 2);
            a1 = *(const float4*)(Arow + k0 + 16 + lkp * 2 + 4);
            w0 = *(const float4*)(Wrow + k0 + 16 + lkp * 2);
            w1 = *(const float4*)(Wrow + k0 + 16 + lkp * 2 + 4);
        }

#pragma unroll
        for (int kp = 0; kp < 8; kp++) {
            union { uint4 u; __half2 h[4]; } ra0, ra1, rw0, rw1;
            ra0.u = *(const uint4*)&As2[kp][ty * 8];
            ra1.u = *(const uint4*)&As2[kp][ty * 8 + 4];
            rw0.u = *(const uint4*)&Ws2[kp][tx * 8];
            rw1.u = *(const uint4*)&Ws2[kp][tx * 8 + 4];
            __half2 ra[8] = {ra0.h[0], ra0.h[1], ra0.h[2], ra0.h[3],
                             ra1.h[0], ra1.h[1], ra1.h[2], ra1.h[3]};
            __half2 rw[8] = {rw0.h[0], rw0.h[1], rw0.h[2], rw0.h[3],
                             rw1.h[0], rw1.h[1], rw1.h[2], rw1.h[3]};
#pragma unroll
            for (int i = 0; i < 8; i++)
#pragma unroll
                for (int j = 0; j < 8; j++)
                    acc2[i][j] = __hfma2(ra[i], rw[j], acc2[i][j]);
        }
        __syncthreads();
    }

    float bias[8];
#pragma unroll
    for (int j = 0; j < 8; j++) bias[j] = bv[tx * 8 + j];

    if (blockIdx.y == 0) {
#pragma unroll
        for (int i = 0; i < 8; i++) {
            int row = m0 + ty * 8 + i;
            if (row < M) {
                float c[8];
#pragma unroll
                for (int j = 0; j < 8; j++)
                    c[j] = __low2float(acc2[i][j]) + __high2float(acc2[i][j]) + bias[j];
                union { __half2 h[4]; uint4 u; } pack;
                pack.h[0] = __floats2half2_rn(c[0], c[1]);
                pack.h[1] = __floats2half2_rn(c[2], c[3]);
                pack.h[2] = __floats2half2_rn(c[4], c[5]);
                pack.h[3] = __floats2half2_rn(c[6], c[7]);
                *(uint4*)&Cxl[(size_t)row * HID + tx * 8] = pack.u;
            }
        }
    } else {
#pragma unroll
        for (int i = 0; i < 8; i++) {
            int row = m0 + ty * 8 + i;
            if (row < M) {
                float* dst = Cxr + (size_t)row * HID + tx * 8;
                *(float4*)(dst + 0) = make_float4(
                    __low2float(acc2[i][0]) + __high2float(acc2[i][0]) + bias[0],
                    __low2float(acc2[i][1]) + __high2float(acc2[i][1]) + bias[1],
                    __low2float(acc2[i][2]) + __high2float(acc2[i][2]) + bias[2],
                    __low2float(acc2[i][3]) + __high2float(acc2[i][3]) + bias[3]);
                *(float4*)(dst + 4) = make_float4(
                    __low2float(acc2[i][4]) + __high2float(acc2[i][4]) + bias[4],
                    __low2float(acc2[i][5]) + __high2float(acc2[i][5]) + bias[5],
                    __low2float(acc2[i][6]) + __high2float(acc2[i][6]) + bias[6],
                    __low2float(acc2[i][7]) + __high2float(acc2[i][7]) + bias[7]);
            }
        }
    }
}

// ---------------- fused node kernel (4-deep prefetch, fp16 xl) ----------------
// mode 0: write out; mode 1: write out + relu; mode 2: pool-atomic (no out write)
__device__ __forceinline__ float lrelu(float x) {
    return fmaxf(x, 0.f) + 0.2f * fminf(x, 0.f);
}

__device__ __forceinline__ float4 xl_load(int node, int lane)
{
    union { uint2 u; __half2 h[2]; } raw;
    raw.u = *(const uint2*)&g_xlh[(size_t)node * HID + 4 * lane];
    float2 f0 = __half22float2(raw.h[0]);
    float2 f1 = __half22float2(raw.h[1]);
    return make_float4(f0.x, f0.y, f1.x, f1.y);
}

__global__ void node_gather(const float* __restrict__ att, const float* __restrict__ bias,
                            float* __restrict__ out, int N, int mode)
{
    int v = (int)((blockIdx.x * (unsigned)blockDim.x + threadIdx.x) >> 5);
    int lane = threadIdx.x & 31;
    if (v >= N) return;

    float4 a4  = ((const float4*)att)[lane];
    float4 xr4 = *(const float4*)&g_xr[(size_t)v * HID + 4 * lane];

    int beg = g_rowstart[v];
    int end = g_rowstart[v + 1];          // deg >= 1 (self-loop guaranteed)
    int deg = end - beg;

    float4 acc = make_float4(0.f, 0.f, 0.f, 0.f);
    float den = 0.f;

    float4 b0, b1, b2, b3;
    {
        int s0 = g_csr[beg];
        int s1 = g_csr[1 < deg ? beg + 1 : beg];
        int s2 = g_csr[2 < deg ? beg + 2 : beg];
        int s3 = g_csr[3 < deg ? beg + 3 : beg];
        b0 = xl_load(s0, lane);
        b1 = xl_load(s1, lane);
        b2 = xl_load(s2, lane);
        b3 = xl_load(s3, lane);
    }

#define NG_STEP(BUF, PF)                                                        \
    {                                                                           \
        float4 xl = BUF;                                                        \
        int pf = (PF);                                                          \
        if (pf < end) {                                                         \
            int sn = g_csr[pf];                                                 \
            BUF = xl_load(sn, lane);                                            \
        }                                                                       \
        float p = lrelu(xl.x + xr4.x) * a4.x                                    \
                + lrelu(xl.y + xr4.y) * a4.y                                    \
                + lrelu(xl.z + xr4.z) * a4.z                                    \
                + lrelu(xl.w + xr4.w) * a4.w;                                   \
        p += __shfl_xor_sync(0xFFFFFFFFu, p, 1);                                \
        p += __shfl_xor_sync(0xFFFFFFFFu, p, 2);                                \
        p += __shfl_xor_sync(0xFFFFFFFFu, p, 4);                                \
        float w = __expf(p);                                                    \
        acc.x += w * xl.x; acc.y += w * xl.y;                                   \
        acc.z += w * xl.z; acc.w += w * xl.w;                                   \
        den += w;                                                               \
    }

    int n4 = (deg >> 2) << 2;
    int e = beg;
    for (; e < beg + n4; e += 4) {
        NG_STEP(b0, e + 4)
        NG_STEP(b1, e + 5)
        NG_STEP(b2, e + 6)
        NG_STEP(b3, e + 7)
    }
    int rem = end - e;
    if (rem > 0) NG_STEP(b0, end)
    if (rem > 1) NG_STEP(b1, end)
    if (rem > 2) NG_STEP(b2, end)
#undef NG_STEP

    float inv = 1.f / (den + 1e-16f);
    const float4 b4 = ((const float4*)bias)[lane];
    float4 o = make_float4(acc.x * inv + b4.x, acc.y * inv + b4.y,
                           acc.z * inv + b4.z, acc.w * inv + b4.w);

    if (mode == 2) {
        // fused global mean pool: accumulate into g_pool[batch[v]]
        int g = g_batch[v];
        float* p = &g_pool[g * HID + 4 * lane];
        asm volatile("red.global.add.v4.f32 [%0], {%1,%2,%3,%4};"
                     :: "l"(p), "f"(o.x), "f"(o.y), "f"(o.z), "f"(o.w)
                     : "memory");
        return;
    }
    if (mode == 1) {
        o.x = fmaxf(o.x, 0.f); o.y = fmaxf(o.y, 0.f);
        o.z = fmaxf(o.z, 0.f); o.w = fmaxf(o.w, 0.f);
    }
    *(float4*)&out[(size_t)v * HID + 4 * lane] = o;
}

// ---------------- head ----------------
__global__ void head_kernel(const float* __restrict__ Wlin, const float* __restrict__ blin,
                            float* __restrict__ out)
{
    int g = threadIdx.x;
    if (g >= NGRAPH) return;
    float cnt = fmaxf(g_cnt[g], 1.f);
    float s = 0.f;
#pragma unroll 4
    for (int k = 0; k < HID; k++) s += g_pool[g * HID + k] * Wlin[k];
    out[g] = s / cnt + blin[0];
}

// ---------------- launch ----------------
extern "C" void kernel_launch(void* const* d_in, const int* in_sizes, int n_in,
                              void* d_out, int out_size)
{
    const float* x     = (const float*)d_in[0];
    const void*  ei    = d_in[1];
    const void*  batch = d_in[2];
    const float* Wl1  = (const float*)d_in[3];
    const float* bl1  = (const float*)d_in[4];
    const float* Wr1  = (const float*)d_in[5];
    const float* br1  = (const float*)d_in[6];
    const float* att1 = (const float*)d_in[7];
    const float* bias1= (const float*)d_in[8];
    const float* Wl2  = (const float*)d_in[9];
    const float* bl2  = (const float*)d_in[10];
    const float* Wr2  = (const float*)d_in[11];
    const float* br2  = (const float*)d_in[12];
    const float* att2 = (const float*)d_in[13];
    const float* bias2= (const float*)d_in[14];
    const float* Wlin = (const float*)d_in[15];
    const float* blin = (const float*)d_in[16];

    int hidden = in_sizes[4];              // 128
    int Fin    = in_sizes[3] / hidden;     // 256
    int N      = in_sizes[0] / Fin;        // 50000
    int E      = in_sizes[1] / 2;          // 1600000
    int ET     = E + N;
    int nb     = (N + SCAN_B - 1) / SCAN_B;

    __half* xlh;
    float *xr, *h1;
    cudaGetSymbolAddress((void**)&xlh, g_xlh);
    cudaGetSymbolAddress((void**)&xr, g_xr);
    cudaGetSymbolAddress((void**)&h1, g_h1);

    int nodeBlocks = (int)(((long long)N * 32 + 255) / 256);
    dim3 gemmGrid((N + 127) / 128, 2);

    static cudaStream_t s_side = nullptr;
    static cudaEvent_t ev_fork = nullptr, ev_csr = nullptr;
    if (s_side == nullptr) {
        cudaStreamCreateWithFlags(&s_side, cudaStreamNonBlocking);
        cudaEventCreateWithFlags(&ev_fork, cudaEventDisableTiming);
        cudaEventCreateWithFlags(&ev_csr, cudaEventDisableTiming);
    }

    // ---- fork: CSR build (+ pool/cnt init) on side stream, gemm1 on main ----
    cudaEventRecord(ev_fork, 0);
    cudaStreamWaitEvent(s_side, ev_fork, 0);

    detect_kernel<<<1, 32, 0, s_side>>>((const unsigned*)ei);
    zero_deg<<<(N + 255) / 256, 256, 0, s_side>>>(N);
    convert_kernel<<<2048, 256, 0, s_side>>>(ei, batch, E, N);
    scan_block<<<nb, SCAN_B, 0, s_side>>>(N);
    scan_partials<<<1, 32, 0, s_side>>>(nb);
    scan_add<<<(N + 255) / 256, 256, 0, s_side>>>(N);
    scatter_kernel<<<2048, 256, 0, s_side>>>(ET);
    cudaEventRecord(ev_csr, s_side);

    gemm_h2<<<gemmGrid, 256>>>(x, Wl1, Wr1, bl1, br1, xlh, xr, N, Fin);
    cudaStreamWaitEvent(0, ev_csr, 0);

    // ---- layer 1 (write h1 + relu) ----
    node_gather<<<nodeBlocks, 256>>>(att1, bias1, h1, N, 1);

    // ---- layer 2 (fused pooling; no h2) ----
    gemm_h2<<<gemmGrid, 256>>>(h1, Wl2, Wr2, bl2, br2, xlh, xr, N, hidden);
    node_gather<<<nodeBlocks, 256>>>(att2, bias2, h1 /*unused*/, N, 2);

    // ---- head ----
    head_kernel<<<1, 64>>>(Wlin, blin, (float*)d_out);
}